// round 9
// baseline (speedup 1.0000x reference)
#include <cuda_runtime.h>

#define BB 8192
#define TT 2048
#define NTHREADS 128           // 4 warps/block -> 1 warp per SMSP
#define NBLOCKS  128           // 512 warps; lane pair per chain
#define CHUNK 8                // timesteps per prefetch chunk

#define MAGIC 12582912.0f      // 1.5*2^23 round-to-nearest-int trick
#define SLUT  128.0f           // table scale: index units per 1.0 of argument
#define INVS  (1.0f / 128.0f)
#define CLMP  2040.0f          // |index| clamp (table covers +-2047)

__device__ __forceinline__ float tanh_ap(float x) {
    float y;
    asm("tanh.approx.f32 %0, %1;" : "=f"(y) : "f"(x));
    return y;
}

// tanh via SMEM LUT + centered linear interp. Input pre-scaled: zs = S*arg.
// Chain: 2xFMNMX(8) + FADD(4) + FSUB(4) + [frac | LOP3+IMAD addr] + LDS.64(29)
// + FFMA(4) ~= 54 cyc, vs ~80 for a dependent MUFU.TANH.
__device__ __forceinline__ float lut_tanh(float zs, const float2* tbl) {
    const float zc = fminf(fmaxf(zs, -CLMP), CLMP);
    const float tb = zc + MAGIC;              // low mantissa bits = round(zc)
    const float rz = tb - MAGIC;
    const float fr = zc - rz;                 // frac in [-0.5, 0.5]
    const int  idx = __float_as_int(tb) & 0xFFF;   // n mod 4096 (0x400000 % 4096 == 0)
    const float2 e = tbl[idx];
    return fmaf(fr, e.y, e.x);
}

// Lane pair (2j, 2j+1) owns one chain; lane parity u owns hidden unit u.
// All activations via LUT; sigma(z) = 0.5*tanh(0.5 z)+0.5 with 0.5*S folded
// into the gate weights; cell state tracked pre-scaled cs = S*c so tanh(c)
// needs no multiply on the critical path.
__global__ void __launch_bounds__(NTHREADS, 1)
lstm_kernel(const float* __restrict__ x,
            const float* __restrict__ h0in,
            const float* __restrict__ c0in,
            const float* __restrict__ w_ih,
            const float* __restrict__ w_hh,
            const float* __restrict__ b_ih,
            const float* __restrict__ b_hh,
            float* __restrict__ out)
{
    __shared__ float2 tbl[4096];

    // Build table: entry k -> n = k (k<2048) else k-4096; x = n/S.
    // Value at center via tanh.approx (err ~1.6e-7); slope = secant over +-0.5.
    for (int k = threadIdx.x; k < 4096; k += NTHREADS) {
        const int   n  = (k < 2048) ? k : k - 4096;
        const float xc = (float)n * INVS;
        const float vm = tanh_ap(xc - 0.5f * INVS);
        const float vp = tanh_ap(xc + 0.5f * INVS);
        tbl[k] = make_float2(tanh_ap(xc), vp - vm);
    }
    __syncthreads();

    const int tid  = blockIdx.x * NTHREADS + threadIdx.x;
    const int pair = tid >> 1;          // chain (batch element)
    const int u    = tid & 1;           // hidden unit owned by this lane
    const int vv   = u ^ 1;             // partner's unit

    // Gate rows (torch order): i=0+u, f=2+u, g=4+u, o=6+u.  q: 0=g,1=i,2=f,3=o
    // sigma gates scaled by 0.5*S, g gate by S (LUT index units).
    float wi0[4], wi1[4], whO[4], whX[4], bs[4];
    const int qrow[4] = {4 + u, 0 + u, 2 + u, 6 + u};   // g, i, f, o
#pragma unroll
    for (int q = 0; q < 4; q++) {
        const int row = qrow[q];
        const float s = (q == 0) ? SLUT : (0.5f * SLUT);
        wi0[q] = s * __ldg(&w_ih[2*row+0]);
        wi1[q] = s * __ldg(&w_ih[2*row+1]);
        whO[q] = s * __ldg(&w_hh[2*row+u]);
        whX[q] = s * __ldg(&w_hh[2*row+vv]);
        bs[q]  = s * (__ldg(&b_ih[row]) + __ldg(&b_hh[row]));
    }

    float h_own = h0in[2*pair + u];
    float cs    = SLUT * c0in[2*pair + u];   // scaled cell state
    float hcs   = 0.5f * cs;                 // running 0.5*cs (off path)

    const float4* __restrict__ xr =
        reinterpret_cast<const float4*>(x) + (size_t)pair * (TT * 2 / 4);

    float4 buf[2][CHUNK / 2];
#pragma unroll
    for (int q = 0; q < CHUNK / 2; q++) buf[0][q] = __ldg(&xr[q]);

#pragma unroll 1
    for (int ch = 0; ch < TT / CHUNK; ch++) {
        const int nb = (ch + 1) & 1;
        if (ch + 1 < TT / CHUNK) {
#pragma unroll
            for (int q = 0; q < CHUNK / 2; q++)
                buf[nb][q] = __ldg(&xr[(ch + 1) * (CHUNK / 2) + q]);
        }
#pragma unroll
        for (int s2 = 0; s2 < CHUNK / 2; s2++) {
            const float4 v4 = buf[ch & 1][s2];
#pragma unroll
            for (int half = 0; half < 2; half++) {
                const float x0 = half ? v4.z : v4.x;
                const float x1 = half ? v4.w : v4.y;

                // Butterfly exchange of h; partner's h is the late operand ->
                // keep it in the OUTERMOST fma of each gate.
                const float h_oth = __shfl_xor_sync(0xffffffffu, h_own, 1);

                float z[4];
#pragma unroll
                for (int q = 0; q < 4; q++) {
                    float t = fmaf(x1, wi1[q], bs[q]);
                    t = fmaf(x0, wi0[q], t);
                    t = fmaf(h_own, whO[q], t);
                    t = fmaf(h_oth, whX[q], t);
                    z[q] = t;
                }

                // Lookups: g, i first (earliest needed), f, then o.
                const float tg = lut_tanh(z[0], tbl);
                const float ti = lut_tanh(z[1], tbl);
                const float tf = lut_tanh(z[2], tbl);
                const float to = lut_tanh(z[3], tbl);

                // cs' = sigma(f)*cs + (S*sigma(i))*tg
                //     = fma(hcs, tf, fma(sip, tg, hcs)),  sip = S/2*ti + S/2
                const float sip = fmaf(0.5f * SLUT, ti, 0.5f * SLUT);
                const float q0  = fmaf(sip, tg, hcs);
                cs = fmaf(hcs, tf, q0);

                // h' = sigma(o)*tanh(c'); LUT input is cs directly (pre-scaled)
                const float tc = lut_tanh(cs, tbl);
                const float so = fmaf(0.5f, to, 0.5f);
                h_own = so * tc;
                hcs = 0.5f * cs;
            }
        }
    }

    out[2*pair + u] = cs * INVS;   // un-scale once
}

extern "C" void kernel_launch(void* const* d_in, const int* in_sizes, int n_in,
                              void* d_out, int out_size) {
    const float* x    = (const float*)d_in[0];
    const float* h0   = (const float*)d_in[1];
    const float* c0   = (const float*)d_in[2];
    const float* w_ih = (const float*)d_in[3];
    const float* w_hh = (const float*)d_in[4];
    const float* b_ih = (const float*)d_in[5];
    const float* b_hh = (const float*)d_in[6];
    lstm_kernel<<<NBLOCKS, NTHREADS>>>(x, h0, c0, w_ih, w_hh, b_ih, b_hh,
                                       (float*)d_out);
}

// round 10
// speedup vs baseline: 1.4200x; 1.4200x over previous
#include <cuda_runtime.h>

#define BB 8192
#define TT 2048
#define NTHREADS 128   // 4 warps/block -> 1 warp per SMSP
#define NBLOCKS  64    // 256 warps; each warp: 16 A-chains + 16 B-chains
#define HALFB    4096  // A-stream chains [0,4096), B-stream [4096,8192)
#define CHUNK 8        // timesteps per prefetch chunk

__device__ __forceinline__ float tanh_ap(float x) {
    float y;
    asm("tanh.approx.f32 %0, %1;" : "=f"(y) : "f"(x));
    return y;
}

// Lane pair (2j,2j+1) owns TWO independent chains (A and B); lane parity u
// owns hidden unit u of each. Interleaving B's ~30 instructions into A's
// scoreboard waits keeps the warp scheduler busy -> no sleep/wakeup penalty
// on dependent MUFU results (the +50cyc that made single-chain L=215).
// MUFU issue per iteration: 10 ops x rt16 = 160 cyc < L, stays sub-binding.
__global__ void __launch_bounds__(NTHREADS, 1)
lstm_kernel(const float* __restrict__ x,
            const float* __restrict__ h0in,
            const float* __restrict__ c0in,
            const float* __restrict__ w_ih,
            const float* __restrict__ w_hh,
            const float* __restrict__ b_ih,
            const float* __restrict__ b_hh,
            float* __restrict__ out)
{
    const int tid  = blockIdx.x * NTHREADS + threadIdx.x;
    const int u    = tid & 1;           // hidden unit owned by this lane
    const int vv   = u ^ 1;             // partner's unit
    const int pA   = tid >> 1;          // chain A (batch element)
    const int pB   = pA + HALFB;        // chain B

    // Gate rows (torch order): i=0+u, f=2+u, g=4+u, o=6+u. q: 0=i,1=g,2=f,3=o
    // sigma(z)=0.5*tanh(0.5z)+0.5 with 0.5 folded into weights/bias (g unscaled).
    // whO multiplies h_own (early operand), whX multiplies h_oth (late, outermost).
    float wi0[4], wi1[4], whO[4], whX[4], bs[4];
    const int qrow[4] = {0 + u, 4 + u, 2 + u, 6 + u};   // i, g, f, o
#pragma unroll
    for (int q = 0; q < 4; q++) {
        const int row = qrow[q];
        const float s = (q == 1) ? 1.0f : 0.5f;
        wi0[q] = s * __ldg(&w_ih[2*row+0]);
        wi1[q] = s * __ldg(&w_ih[2*row+1]);
        whO[q] = s * __ldg(&w_hh[2*row+u]);
        whX[q] = s * __ldg(&w_hh[2*row+vv]);
        bs[q]  = s * (__ldg(&b_ih[row]) + __ldg(&b_hh[row]));
    }

    float hA = h0in[2*pA + u], cA = c0in[2*pA + u], hcA = 0.5f * cA;
    float hB = h0in[2*pB + u], cB = c0in[2*pB + u], hcB = 0.5f * cB;

    const float4* __restrict__ xrA =
        reinterpret_cast<const float4*>(x) + (size_t)pA * (TT * 2 / 4);
    const float4* __restrict__ xrB =
        reinterpret_cast<const float4*>(x) + (size_t)pB * (TT * 2 / 4);

    float4 bufA[2][CHUNK / 2], bufB[2][CHUNK / 2];
#pragma unroll
    for (int q = 0; q < CHUNK / 2; q++) {
        bufA[0][q] = __ldg(&xrA[q]);
        bufB[0][q] = __ldg(&xrB[q]);
    }

#pragma unroll 1
    for (int ch = 0; ch < TT / CHUNK; ch++) {
        const int nb = (ch + 1) & 1;
        if (ch + 1 < TT / CHUNK) {
#pragma unroll
            for (int q = 0; q < CHUNK / 2; q++) {
                bufA[nb][q] = __ldg(&xrA[(ch + 1) * (CHUNK / 2) + q]);
                bufB[nb][q] = __ldg(&xrB[(ch + 1) * (CHUNK / 2) + q]);
            }
        }
#pragma unroll
        for (int s2 = 0; s2 < CHUNK / 2; s2++) {
            const float4 vA = bufA[ch & 1][s2];
            const float4 vB = bufB[ch & 1][s2];
#pragma unroll
            for (int half = 0; half < 2; half++) {
                const float xA0 = half ? vA.z : vA.x;
                const float xA1 = half ? vA.w : vA.y;
                const float xB0 = half ? vB.z : vB.x;
                const float xB1 = half ? vB.w : vB.y;

                // Exchanges for both chains (independent; back-to-back issue).
                const float hAo = __shfl_xor_sync(0xffffffffu, hA, 1);
                const float hBo = __shfl_xor_sync(0xffffffffu, hB, 1);

                float zA[4], zB[4];
#pragma unroll
                for (int q = 0; q < 4; q++) {
                    float tA = fmaf(xA1, wi1[q], bs[q]);
                    float tB = fmaf(xB1, wi1[q], bs[q]);
                    tA = fmaf(xA0, wi0[q], tA);
                    tB = fmaf(xB0, wi0[q], tB);
                    tA = fmaf(hA,  whO[q], tA);
                    tB = fmaf(hB,  whO[q], tB);
                    zA[q] = fmaf(hAo, whX[q], tA);
                    zB[q] = fmaf(hBo, whX[q], tB);
                }

                // MUFUs interleaved A/B: c-path gates (i,g,f) first, o last.
                const float tiA = tanh_ap(zA[0]);
                const float tiB = tanh_ap(zB[0]);
                const float tgA = tanh_ap(zA[1]);
                const float tgB = tanh_ap(zB[1]);
                const float tfA = tanh_ap(zA[2]);
                const float tfB = tanh_ap(zB[2]);
                const float toA = tanh_ap(zA[3]);
                const float toB = tanh_ap(zB[3]);

                // c' = (0.5c)*t_f + (0.5c + sigma(i)*t_g), sigma = 0.5 t + 0.5
                const float siA = fmaf(0.5f, tiA, 0.5f);
                const float siB = fmaf(0.5f, tiB, 0.5f);
                const float qA  = fmaf(siA, tgA, hcA);
                const float qB  = fmaf(siB, tgB, hcB);
                cA = fmaf(hcA, tfA, qA);
                cB = fmaf(hcB, tfB, qB);

                const float tcA = tanh_ap(cA);
                const float tcB = tanh_ap(cB);
                const float soA = fmaf(0.5f, toA, 0.5f);
                const float soB = fmaf(0.5f, toB, 0.5f);
                hA = soA * tcA;
                hB = soB * tcB;
                hcA = 0.5f * cA;
                hcB = 0.5f * cB;
            }
        }
    }

    out[2*pA + u] = cA;
    out[2*pB + u] = cB;
}

extern "C" void kernel_launch(void* const* d_in, const int* in_sizes, int n_in,
                              void* d_out, int out_size) {
    const float* x    = (const float*)d_in[0];
    const float* h0   = (const float*)d_in[1];
    const float* c0   = (const float*)d_in[2];
    const float* w_ih = (const float*)d_in[3];
    const float* w_hh = (const float*)d_in[4];
    const float* b_ih = (const float*)d_in[5];
    const float* b_hh = (const float*)d_in[6];
    lstm_kernel<<<NBLOCKS, NTHREADS>>>(x, h0, c0, w_ih, w_hh, b_ih, b_hh,
                                       (float*)d_out);
}

// round 11
// speedup vs baseline: 1.5459x; 1.0886x over previous
#include <cuda_runtime.h>

#define BB 8192
#define TT 2048
#define NTHREADS 256   // 8 warps/block -> 2 warps per SMSP (stall-filling partner)
#define NBLOCKS  64    // 16384 threads; lane pair per chain -> 8192 chains
#define CHUNK 8        // timesteps per prefetch chunk

__device__ __forceinline__ float tanh_ap(float x) {
    float y;
    asm("tanh.approx.f32 %0, %1;" : "=f"(y) : "f"(x));
    return y;
}

// Lane pair (2j,2j+1) owns ONE chain; lane parity u owns hidden unit u.
// 2 warps per SMSP: the partner warp fills every scoreboard wait, removing
// the single-warp sleep/wakeup penalty (R9 measured the wakeup-free chain at
// 149 cyc/step). Binding resource becomes MUFU throughput:
//   2 warps x 5 TANH x rt16 = 160 cyc per SMSP per step-pair
// -> predicted period ~170 cyc vs 215 (R4) / 245 (R0).
__global__ void __launch_bounds__(NTHREADS, 1)
lstm_kernel(const float* __restrict__ x,
            const float* __restrict__ h0in,
            const float* __restrict__ c0in,
            const float* __restrict__ w_ih,
            const float* __restrict__ w_hh,
            const float* __restrict__ b_ih,
            const float* __restrict__ b_hh,
            float* __restrict__ out)
{
    const int tid  = blockIdx.x * NTHREADS + threadIdx.x;
    const int u    = tid & 1;           // hidden unit owned by this lane
    const int vv   = u ^ 1;             // partner's unit
    const int pair = tid >> 1;          // chain (batch element)

    // Gate rows (torch order): i=0+u, f=2+u, g=4+u, o=6+u. q: 0=i,1=g,2=f,3=o
    // sigma(z)=0.5*tanh(0.5z)+0.5 with 0.5 folded into weights/bias (g unscaled).
    // whO multiplies h_own (early operand), whX multiplies h_oth (late, outermost).
    float wi0[4], wi1[4], whO[4], whX[4], bs[4];
    const int qrow[4] = {0 + u, 4 + u, 2 + u, 6 + u};   // i, g, f, o
#pragma unroll
    for (int q = 0; q < 4; q++) {
        const int row = qrow[q];
        const float s = (q == 1) ? 1.0f : 0.5f;
        wi0[q] = s * __ldg(&w_ih[2*row+0]);
        wi1[q] = s * __ldg(&w_ih[2*row+1]);
        whO[q] = s * __ldg(&w_hh[2*row+u]);
        whX[q] = s * __ldg(&w_hh[2*row+vv]);
        bs[q]  = s * (__ldg(&b_ih[row]) + __ldg(&b_hh[row]));
    }

    float h_own = h0in[2*pair + u];
    float c     = c0in[2*pair + u];
    float hc    = 0.5f * c;             // running 0.5*c (off critical path)

    const float4* __restrict__ xr =
        reinterpret_cast<const float4*>(x) + (size_t)pair * (TT * 2 / 4);

    float4 buf[2][CHUNK / 2];
#pragma unroll
    for (int q = 0; q < CHUNK / 2; q++) buf[0][q] = __ldg(&xr[q]);

#pragma unroll 1
    for (int ch = 0; ch < TT / CHUNK; ch++) {
        const int nb = (ch + 1) & 1;
        if (ch + 1 < TT / CHUNK) {
#pragma unroll
            for (int q = 0; q < CHUNK / 2; q++)
                buf[nb][q] = __ldg(&xr[(ch + 1) * (CHUNK / 2) + q]);
        }
#pragma unroll
        for (int s2 = 0; s2 < CHUNK / 2; s2++) {
            const float4 v4 = buf[ch & 1][s2];
#pragma unroll
            for (int half = 0; half < 2; half++) {
                const float x0 = half ? v4.z : v4.x;
                const float x1 = half ? v4.w : v4.y;

                // Single butterfly exchange; partner's h is the late operand ->
                // outermost fma of each gate.
                const float h_oth = __shfl_xor_sync(0xffffffffu, h_own, 1);

                float z[4];
#pragma unroll
                for (int q = 0; q < 4; q++) {
                    float t = fmaf(x1, wi1[q], bs[q]);
                    t = fmaf(x0, wi0[q], t);
                    t = fmaf(h_own, whO[q], t);
                    z[q] = fmaf(h_oth, whX[q], t);
                }

                // MUFU order: c-path gates (i, g, f) first, o last.
                const float ti = tanh_ap(z[0]);
                const float tg = tanh_ap(z[1]);
                const float tf = tanh_ap(z[2]);
                const float to = tanh_ap(z[3]);

                // c' = (0.5c)*t_f + (0.5c + sigma(i)*t_g), sigma = 0.5 t + 0.5
                const float si = fmaf(0.5f, ti, 0.5f);
                const float q0 = fmaf(si, tg, hc);
                c = fmaf(hc, tf, q0);

                const float tc = tanh_ap(c);
                const float so = fmaf(0.5f, to, 0.5f);
                h_own = so * tc;
                hc = 0.5f * c;
            }
        }
    }

    out[2*pair + u] = c;
}

extern "C" void kernel_launch(void* const* d_in, const int* in_sizes, int n_in,
                              void* d_out, int out_size) {
    const float* x    = (const float*)d_in[0];
    const float* h0   = (const float*)d_in[1];
    const float* c0   = (const float*)d_in[2];
    const float* w_ih = (const float*)d_in[3];
    const float* w_hh = (const float*)d_in[4];
    const float* b_ih = (const float*)d_in[5];
    const float* b_hh = (const float*)d_in[6];
    lstm_kernel<<<NBLOCKS, NTHREADS>>>(x, h0, c0, w_ih, w_hh, b_ih, b_hh,
                                       (float*)d_out);
}

// round 12
// speedup vs baseline: 1.9162x; 1.2396x over previous
#include <cuda_runtime.h>

#define BB 8192
#define TT 2048
#define NTHREADS 128           // 4 warps/block -> 1 warp per SMSP
#define NBLOCKS  128           // 512 warps; lane pair per chain
#define CHUNK 8                // timesteps per prefetch chunk

__device__ __forceinline__ float tanh_ap(float x) {
    float y;
    asm("tanh.approx.f32 %0, %1;" : "=f"(y) : "f"(x));
    return y;
}

// Lane pair (2j,2j+1) owns one chain; lane parity u owns hidden unit u.
// DEFERRED-h FORM: h = sigma(o)*tanh(c) is never materialized. sigma(o) is
// ready ~60cyc before tanh(c) (its MUFU issues first), so the products
// whO' = whO*sigma_o(own), whX' = whX*sigma_o(partner) are computed DURING
// the tanh(c) wait, off the critical path. Next step's gates are then
//   z = fma(whX', tc_oth, fma(whO', tc, xpart))
// -> path from tc: shfl(26) || fma(4), +fma(4). Removes the h-multiply and
// one z-fma stage from the recurrence cycle:
//   old: tc -> mul(4) -> shfl(26) -> 2 fma(8) -> tanh ...   (~215 total)
//   new: tc -> shfl(26) -> fma(4)+fma(4) -> tanh ...        (~185 total)
__global__ void __launch_bounds__(NTHREADS, 1)
lstm_kernel(const float* __restrict__ x,
            const float* __restrict__ h0in,
            const float* __restrict__ c0in,
            const float* __restrict__ w_ih,
            const float* __restrict__ w_hh,
            const float* __restrict__ b_ih,
            const float* __restrict__ b_hh,
            float* __restrict__ out)
{
    const int tid  = blockIdx.x * NTHREADS + threadIdx.x;
    const int u    = tid & 1;           // hidden unit owned by this lane
    const int vv   = u ^ 1;             // partner's unit
    const int pair = tid >> 1;          // chain (batch element)

    // Gate order q: 0=o, 1=i, 2=g, 3=f  (rows 6+u, 0+u, 4+u, 2+u).
    // o FIRST (sigma_o needed earliest for the weight prep), f LAST (only one
    // fma from tanh(f) to c'). sigma(z)=0.5*tanh(0.5z)+0.5, 0.5 folded into
    // weights/bias for o,i,f; g unscaled.
    float wi0[4], wi1[4], whO[4], whX[4], bs[4];
    const int qrow[4] = {6 + u, 0 + u, 4 + u, 2 + u};   // o, i, g, f
#pragma unroll
    for (int q = 0; q < 4; q++) {
        const int row = qrow[q];
        const float s = (q == 2) ? 1.0f : 0.5f;
        wi0[q] = s * __ldg(&w_ih[2*row+0]);
        wi1[q] = s * __ldg(&w_ih[2*row+1]);
        whO[q] = s * __ldg(&w_hh[2*row+u]);
        whX[q] = s * __ldg(&w_hh[2*row+vv]);
        bs[q]  = s * (__ldg(&b_ih[row]) + __ldg(&b_hh[row]));
    }

    float c  = c0in[2*pair + u];
    float hc = 0.5f * c;                // running 0.5*c (off critical path)

    // Deferred-h state: tc carries tanh(c) of the PREVIOUS step scaled into
    // h via the prepped weights. Bootstrap: sigma_o := 1, tc := h0, so the
    // first step's prepped weights are the raw whO/whX and z sees h0 exactly.
    float tc = h0in[2*pair + u];
    float whOp[4], whXp[4];
#pragma unroll
    for (int q = 0; q < 4; q++) { whOp[q] = whO[q]; whXp[q] = whX[q]; }

    const float4* __restrict__ xr =
        reinterpret_cast<const float4*>(x) + (size_t)pair * (TT * 2 / 4);

    float4 buf[2][CHUNK / 2];
#pragma unroll
    for (int q = 0; q < CHUNK / 2; q++) buf[0][q] = __ldg(&xr[q]);

#pragma unroll 1
    for (int ch = 0; ch < TT / CHUNK; ch++) {
        const int nb = (ch + 1) & 1;
        if (ch + 1 < TT / CHUNK) {
#pragma unroll
            for (int q = 0; q < CHUNK / 2; q++)
                buf[nb][q] = __ldg(&xr[(ch + 1) * (CHUNK / 2) + q]);
        }
#pragma unroll
        for (int s2 = 0; s2 < CHUNK / 2; s2++) {
            const float4 v4 = buf[ch & 1][s2];
#pragma unroll
            for (int half = 0; half < 2; half++) {
                const float x0 = half ? v4.z : v4.x;
                const float x1 = half ? v4.w : v4.y;

                // Exchange tanh(c) — first op on the critical path.
                const float tc_oth = __shfl_xor_sync(0xffffffffu, tc, 1);

                // z_q: xpart (hoistable) + prepped-weight taps of tc, tc_oth.
                float z[4];
#pragma unroll
                for (int q = 0; q < 4; q++) {
                    float t = fmaf(x1, wi1[q], bs[q]);
                    t = fmaf(x0, wi0[q], t);
                    t = fmaf(tc, whOp[q], t);
                    z[q] = fmaf(tc_oth, whXp[q], t);
                }

                // MUFU order: o (prep needs it), i, g, f (c needs it last).
                const float to = tanh_ap(z[0]);
                const float ti = tanh_ap(z[1]);
                const float tg = tanh_ap(z[2]);
                const float tf = tanh_ap(z[3]);

                // sigma_o ready first; exchange + weight prep run under the
                // remaining gate tanhs and the tanh(c) below (off path).
                const float so     = fmaf(0.5f, to, 0.5f);
                const float so_oth = __shfl_xor_sync(0xffffffffu, so, 1);

                // c' = (0.5c)*t_f + (0.5c + sigma(i)*t_g)
                const float si = fmaf(0.5f, ti, 0.5f);
                const float q0 = fmaf(si, tg, hc);
                c = fmaf(hc, tf, q0);

                tc = tanh_ap(c);     // critical path; prep hides under it
#pragma unroll
                for (int q = 0; q < 4; q++) {
                    whOp[q] = whO[q] * so;
                    whXp[q] = whX[q] * so_oth;
                }
                hc = 0.5f * c;
            }
        }
    }

    out[2*pair + u] = c;
}

extern "C" void kernel_launch(void* const* d_in, const int* in_sizes, int n_in,
                              void* d_out, int out_size) {
    const float* x    = (const float*)d_in[0];
    const float* h0   = (const float*)d_in[1];
    const float* c0   = (const float*)d_in[2];
    const float* w_ih = (const float*)d_in[3];
    const float* w_hh = (const float*)d_in[4];
    const float* b_ih = (const float*)d_in[5];
    const float* b_hh = (const float*)d_in[6];
    lstm_kernel<<<NBLOCKS, NTHREADS>>>(x, h0, c0, w_ih, w_hh, b_ih, b_hh,
                                       (float*)d_out);
}